// round 14
// baseline (speedup 1.0000x reference)
#include <cuda_runtime.h>
#include <cuda_fp16.h>
#include <math.h>

#define NNODE 50000
#define EMB 35
#define DEG 32
#define NBH 36     // halves per nb row: 35 ch + s_b(fp16) at slot 35 = 72B = 9 ull
#define MSTR 36    // g_m row stride (floats)

typedef unsigned long long ull;

// ---------------- scratch (device globals; no runtime allocation) ----------------
__device__ __half g_nbh[4][NNODE * NBH];   // fp16 transformed rows; slot 35 carries s_b
__device__ float  g_sa[4][NNODE];          // src-side attention score
__device__ float  g_m [4][NNODE * MSTR];   // aggregation results (padded rows)

// ---------------- packed f32x2 helpers ----------------
static __device__ __forceinline__ ull pack2(float a, float b) {
    ull r;
    unsigned int lo = __float_as_uint(a), hi = __float_as_uint(b);
    asm("mov.b64 %0, {%1, %2};" : "=l"(r) : "r"(lo), "r"(hi));
    return r;
}
static __device__ __forceinline__ void unpack2(ull v, float &a, float &b) {
    unsigned int lo, hi;
    asm("mov.b64 {%0, %1}, %2;" : "=r"(lo), "=r"(hi) : "l"(v));
    a = __uint_as_float(lo);
    b = __uint_as_float(hi);
}
#define FMA2(d, a, b, c) \
    asm("fma.rn.f32x2 %0, %1, %2, %3;" : "=l"(d) : "l"(a), "l"(b), "l"(c))

// ---------------- kernel args ----------------
struct TArgs {
    const float* fa;
    const float* fb;
    const float* W[4];
    const float* b[4];
    const float* att[4];
};
struct AArgs {
    const int* dst[4];
};

// =====================================================================
// Kernel 1: side-merged transform. Side s stages farr = (s ? fb : fa) ONCE,
// then serves:
//   - GEMM (nb fp16 + s_b in slot 35) for the 2 jobs with fsrc == farr
//     (jobs 2,3 for fa; 0,1 for fb)
//   - s_a dots for the 2 jobs with fdst == farr (jobs 0,1 for fa; 2,3 for fb)
// 4 threads per row: q = jj*2 + half; each owns 9 pairs of one job's half.
// 512 threads = 128 rows.
// =====================================================================
__global__ __launch_bounds__(512) void transform_kernel(TArgs args) {
    const int s   = blockIdx.y;
    const int jg0 = s ? 0 : 2;   // GEMM jobs jg0, jg0+1
    const int ja0 = s ? 2 : 0;   // s_a jobs ja0, ja0+1
    const float* __restrict__ farr = s ? args.fb : args.fa;

    __shared__ __align__(16) float Xs[128 * 37];   // 18944B staged rows
    __shared__ __align__(16) ull wp[2][EMB * 20];  // 11200B padded packed W
    __shared__ __align__(16) ull bp[2][18];
    __shared__ __align__(16) ull ahp[2][18];
    __shared__ __align__(16) float alo[2][36];

    const int tid = threadIdx.x;
    for (int idx = tid; idx < 2 * EMB * 18; idx += 512) {
        int jj = idx / (EMB * 18);
        int r  = idx - jj * (EMB * 18);
        int k = r / 18, i = r % 18, c = 2 * i;
        const float* W = args.W[jg0 + jj];
        wp[jj][k * 20 + i + (i >= 9 ? 1 : 0)] =
            pack2(W[k * EMB + c], (c + 1 < EMB) ? W[k * EMB + c + 1] : 0.0f);
    }
    if (tid < 36) {
        int jj = tid / 18, i = tid % 18, c = 2 * i;
        const float* bv  = args.b[jg0 + jj];
        const float* att = args.att[jg0 + jj];
        bp[jj][i]  = pack2(bv[c],        (c + 1 < EMB) ? bv[c + 1]        : 0.0f);
        ahp[jj][i] = pack2(att[EMB + c], (c + 1 < EMB) ? att[EMB + c + 1] : 0.0f);
    }
    if (tid >= 64 && tid < 136) {
        int t = tid - 64;
        int jj = t / 36, k = t % 36;
        alo[jj][k] = (k < EMB) ? args.att[ja0 + jj][k] : 0.0f;
    }

    const int base  = blockIdx.x * 128;
    const int nrows = min(128, NNODE - base);
    const int total = nrows * EMB;
    {
        const float* __restrict__ src = farr + base * EMB;
        for (int g = tid; g < total; g += 512)
            Xs[(g / EMB) * 37 + (g % EMB)] = src[g];
    }
    __syncthreads();

    const int row_l = tid >> 2;
    const int q     = tid & 3;
    const int jj    = q >> 1;
    const int half  = q & 1;
    const bool valid = (row_l < nrows);
    const int rl  = valid ? row_l : 0;    // clamp; warp stays converged
    const int row = base + rl;
    const float* xrs = Xs + rl * 37;

    // ---- GEMM: this thread owns job jg0+jj, channel pairs [9*half, 9*half+9) ----
    ull acc[9];
#pragma unroll
    for (int i = 0; i < 9; i++) acc[i] = bp[jj][9 * half + i];

    const ull* wb = wp[jj] + 10 * half;
#pragma unroll 5
    for (int k = 0; k < EMB; k++) {
        float xv = xrs[k];
        ull xx = pack2(xv, xv);
        const ull* wr = wb + k * 20;
        const ulonglong2* w2v = reinterpret_cast<const ulonglong2*>(wr);
#pragma unroll
        for (int i = 0; i < 4; i++) {
            ulonglong2 wv = w2v[i];
            FMA2(acc[2 * i],     wv.x, xx, acc[2 * i]);
            FMA2(acc[2 * i + 1], wv.y, xx, acc[2 * i + 1]);
        }
        FMA2(acc[8], wr[8], xx, acc[8]);
    }

    // ---- s_b: partial over this half, combine with partner half (tid^1) ----
    float ps;
    {
        ull sp = 0ull;
#pragma unroll
        for (int i = 0; i < 9; i++) FMA2(sp, acc[i], ahp[jj][9 * half + i], sp);
        float x0, y0;
        unpack2(sp, x0, y0);
        ps = x0 + y0;
        ps += __shfl_xor_sync(0xffffffffu, ps, 1);
    }

    // ---- fp16 store (9 uints); half1's last pair carries (ch34, s_b) ----
    if (valid) {
        unsigned int* r =
            reinterpret_cast<unsigned int*>(&g_nbh[jg0 + jj][row * NBH]) + 9 * half;
#pragma unroll
        for (int i = 0; i < 9; i++) {
            float f0, f1;
            unpack2(acc[i], f0, f1);
            if (half == 1 && i == 8) f1 = ps;    // slot 35 := s_b
            __half2 h = __floats2half2_rn(f0, f1);
            r[i] = *reinterpret_cast<unsigned int*>(&h);
        }
    }

    // ---- s_a: threads q=0,1 compute the two fdst jobs' dots ----
    if (q < 2) {
        float sa = 0.0f;
        const float* al = alo[q];
#pragma unroll 7
        for (int k = 0; k < EMB; k++) sa = fmaf(xrs[k], al[k], sa);
        if (valid) g_sa[ja0 + q][row] = sa;
    }
}

// =====================================================================
// Kernel 2 (unchanged): attention aggregation. One warp per node.
// =====================================================================
__global__ __launch_bounds__(256) void agg_kernel(AArgs args) {
    const int jid = blockIdx.y;
    const __half* __restrict__ nbh = g_nbh[jid];
    const ull* __restrict__ nb = reinterpret_cast<const ull*>(nbh);
    const float* __restrict__ sav = g_sa[jid];
    const int*   __restrict__ dst = args.dst[jid];
    float* __restrict__ m = g_m[jid];

    __shared__ float sw[8][36];
    __shared__ int   soff[8][36];

    const int wid  = threadIdx.x >> 5;
    const int lane = threadIdx.x & 31;
    const int node = blockIdx.x * 8 + wid;
    if (node >= NNODE) return;

    const int d = dst[node * DEG + lane];
    float sb = __half2float(nbh[d * NBH + 35]);
    float x = sav[node] + sb;
    float e = (x > 0.0f) ? x : 0.1f * expm1f(x);   // elu(alpha=0.1)
    float w = expf(e);

    float wsum = w;
#pragma unroll
    for (int o = 16; o; o >>= 1) wsum += __shfl_xor_sync(0xffffffffu, wsum, o);

    sw[wid][lane]   = w;
    soff[wid][lane] = d * 9;
    if (lane == 0) { sw[wid][32] = 0.0f; soff[wid][32] = 0; }
    __syncwarp();

    const int sub   = (lane < 27) ? (lane / 9) : 2;
    const int piece = (lane < 27) ? (lane % 9) : (lane - 27);

    float a0 = 0.0f, a1 = 0.0f, a2 = 0.0f, a3 = 0.0f;
#pragma unroll
    for (int it = 0; it < 11; it++) {
        int j = it * 3 + sub;
        float wj = sw[wid][j];
        ull v = nb[soff[wid][j] + piece];
        unsigned int lo, hi;
        asm("mov.b64 {%0, %1}, %2;" : "=r"(lo), "=r"(hi) : "l"(v));
        float2 f0 = __half22float2(*reinterpret_cast<__half2*>(&lo));
        float2 f1 = __half22float2(*reinterpret_cast<__half2*>(&hi));
        a0 = fmaf(wj, f0.x, a0);
        a1 = fmaf(wj, f0.y, a1);
        a2 = fmaf(wj, f1.x, a2);
        a3 = fmaf(wj, f1.y, a3);
    }

    {
        float t, u;
        t = __shfl_down_sync(0xffffffffu, a0, 9);
        u = __shfl_down_sync(0xffffffffu, a0, 18);
        a0 += t + u;
        t = __shfl_down_sync(0xffffffffu, a1, 9);
        u = __shfl_down_sync(0xffffffffu, a1, 18);
        a1 += t + u;
        t = __shfl_down_sync(0xffffffffu, a2, 9);
        u = __shfl_down_sync(0xffffffffu, a2, 18);
        a2 += t + u;
        t = __shfl_down_sync(0xffffffffu, a3, 9);
        u = __shfl_down_sync(0xffffffffu, a3, 18);
        a3 += t + u;
    }

    if (lane < 9) {
        float inv = 1.0f / wsum;
        float4 o = make_float4(a0 * inv, a1 * inv, a2 * inv, a3 * inv);
        *reinterpret_cast<float4*>(m + node * MSTR + 4 * lane) = o;
    }
}

// =====================================================================
// Kernel 3 (unchanged): register-tiled update, fp16 X/H, LDS.128 W reads.
// =====================================================================
__global__ __launch_bounds__(256, 3) void update_kernel(
    const float* __restrict__ fa, const float* __restrict__ fb,
    const float* __restrict__ W1, const float* __restrict__ b1,
    const float* __restrict__ alpha_p,
    const float* __restrict__ W2, const float* __restrict__ b2,
    float* __restrict__ out)
{
    __shared__ __align__(16) __half Xh[105 * 132];  // 27720B: Xh, then Hh
    __shared__ __align__(16) ull   w1p[105 * 40];   // 33600B padded packed W1
    __shared__ __align__(16) ull   w2p[70 * 20];    // 11200B padded packed W2
    __shared__ __align__(16) ull   b1p[36];
    __shared__ __align__(16) ull   b2p[18];

    const int tid = threadIdx.x;
    for (int i = tid; i < 105 * 36; i += 256) {
        int k = i / 36, j = i % 36;
        int c = 2 * j;
        float v0 = (c < 70)     ? W1[k * 70 + c]     : 0.0f;
        float v1 = (c + 1 < 70) ? W1[k * 70 + c + 1] : 0.0f;
        w1p[k * 40 + j + j / 9] = pack2(v0, v1);
    }
    for (int i = tid; i < 70 * 18; i += 256) {
        int k = i / 18, p = i % 18;
        int c = 2 * p;
        int slot = p + (p >= 5 ? 1 : 0) + (p >= 10 ? 1 : 0);
        w2p[k * 20 + slot] =
            pack2(W2[k * EMB + c], (c + 1 < EMB) ? W2[k * EMB + c + 1] : 0.0f);
    }
    if (tid < 36) {
        int c = 2 * tid;
        b1p[tid] = pack2((c < 70) ? b1[c] : 0.0f, (c + 1 < 70) ? b1[c + 1] : 0.0f);
    }
    if (tid < 18) {
        int c = 2 * tid;
        b2p[tid] = pack2(b2[c], (c + 1 < EMB) ? b2[c + 1] : 0.0f);
    }

    const int base = blockIdx.x * 128;

    for (int g = tid; g < 128 * 105; g += 256) {
        int nl = g / 105;
        int k  = g - nl * 105;
        int n  = base + nl;
        float v = 0.0f;
        if (n < 2 * NNODE) {
            if (n < NNODE) {
                if (k < EMB)          v = fa[n * EMB + k];
                else if (k < 2 * EMB) v = g_m[0][n * MSTR + (k - EMB)];
                else                  v = g_m[1][n * MSTR + (k - 2 * EMB)];
            } else {
                int nn = n - NNODE;
                if (k < EMB)          v = fb[nn * EMB + k];
                else if (k < 2 * EMB) v = g_m[2][nn * MSTR + (k - EMB)];
                else                  v = g_m[3][nn * MSTR + (k - 2 * EMB)];
            }
        }
        Xh[k * 132 + nl] = __float2half_rn(v);
    }
    __syncthreads();

    const int cg = tid >> 6;
    const int ng = tid & 63;
    const int n0 = base + 2 * ng;
    const float alpha = __ldg(alpha_p);

    ull acc0[9], acc1[9];
#pragma unroll
    for (int i = 0; i < 9; i++) { acc0[i] = b1p[9 * cg + i]; acc1[i] = acc0[i]; }

    const ull* wbase = w1p + 10 * cg;
    for (int k = 0; k < 105; k++) {
        __half2 hv = *reinterpret_cast<const __half2*>(&Xh[k * 132 + 2 * ng]);
        float2 xv = __half22float2(hv);
        ull xx0 = pack2(xv.x, xv.x);
        ull xx1 = pack2(xv.y, xv.y);
        const ull* wr = wbase + k * 40;
        const ulonglong2* wv2 = reinterpret_cast<const ulonglong2*>(wr);
#pragma unroll
        for (int i = 0; i < 4; i++) {
            ulonglong2 wv = wv2[i];
            FMA2(acc0[2 * i],     wv.x, xx0, acc0[2 * i]);
            FMA2(acc1[2 * i],     wv.x, xx1, acc1[2 * i]);
            FMA2(acc0[2 * i + 1], wv.y, xx0, acc0[2 * i + 1]);
            FMA2(acc1[2 * i + 1], wv.y, xx1, acc1[2 * i + 1]);
        }
        {
            ull w = wr[8];
            FMA2(acc0[8], w, xx0, acc0[8]);
            FMA2(acc1[8], w, xx1, acc1[8]);
        }
    }
    __syncthreads();

#pragma unroll
    for (int i = 0; i < 9; i++) {
        int c = 18 * cg + 2 * i;
        float h0, h1, g0, g1;
        unpack2(acc0[i], h0, h1);
        unpack2(acc1[i], g0, g1);
        h0 = (h0 > 0.0f) ? h0 : alpha * h0;
        h1 = (h1 > 0.0f) ? h1 : alpha * h1;
        g0 = (g0 > 0.0f) ? g0 : alpha * g0;
        g1 = (g1 > 0.0f) ? g1 : alpha * g1;
        __half2 p0 = __floats2half2_rn(h0, g0);
        __half2 p1 = __floats2half2_rn(h1, g1);
        *reinterpret_cast<__half2*>(&Xh[c * 132 + 2 * ng])       = p0;
        *reinterpret_cast<__half2*>(&Xh[(c + 1) * 132 + 2 * ng]) = p1;
    }
    __syncthreads();

    const int p0 = (cg < 2) ? cg * 5 : 10 + (cg - 2) * 4;
    const int np = (cg < 2) ? 5 : 4;
    const int soff = (cg < 2) ? cg * 6 : 12 + (cg - 2) * 4;

    ull a20[5], a21[5];
#pragma unroll
    for (int q = 0; q < 5; q++) {
        ull b = (q < np) ? b2p[p0 + q] : 0ull;
        a20[q] = b;
        a21[q] = b;
    }

    const ull* w2base = w2p + soff;
    for (int k = 0; k < 70; k++) {
        __half2 hv = *reinterpret_cast<const __half2*>(&Xh[k * 132 + 2 * ng]);
        float2 xv = __half22float2(hv);
        ull xx0 = pack2(xv.x, xv.x);
        ull xx1 = pack2(xv.y, xv.y);
        const ull* wr = w2base + k * 20;
        const ulonglong2* wv2 = reinterpret_cast<const ulonglong2*>(wr);
#pragma unroll
        for (int i = 0; i < 2; i++) {
            ulonglong2 wv = wv2[i];
            FMA2(a20[2 * i],     wv.x, xx0, a20[2 * i]);
            FMA2(a21[2 * i],     wv.x, xx1, a21[2 * i]);
            FMA2(a20[2 * i + 1], wv.y, xx0, a20[2 * i + 1]);
            FMA2(a21[2 * i + 1], wv.y, xx1, a21[2 * i + 1]);
        }
        if (np == 5) {
            ull w = wr[4];
            FMA2(a20[4], w, xx0, a20[4]);
            FMA2(a21[4], w, xx1, a21[4]);
        }
    }

#pragma unroll
    for (int p = 0; p < 2; p++) {
        int n = n0 + p;
        if (n < 2 * NNODE) {
            float* orow = out + n * EMB;
#pragma unroll
            for (int q = 0; q < 5; q++) {
                if (q < np) {
                    float v0, v1;
                    unpack2(p ? a21[q] : a20[q], v0, v1);
                    int c = 2 * (p0 + q);
                    orow[c] = v0;
                    if (c + 1 < EMB) orow[c + 1] = v1;
                }
            }
        }
    }
}

// =====================================================================
// launch
// =====================================================================
extern "C" void kernel_launch(void* const* d_in, const int* in_sizes, int n_in,
                              void* d_out, int out_size) {
    const float* fa = (const float*)d_in[0];
    const float* fb = (const float*)d_in[1];

    TArgs t;
    t.fa = fa;
    t.fb = fb;
    for (int j = 0; j < 4; j++) {
        t.W[j]   = (const float*)d_in[6 + 3 * j];
        t.b[j]   = (const float*)d_in[7 + 3 * j];
        t.att[j] = (const float*)d_in[8 + 3 * j];
    }
    AArgs a;
    a.dst[0] = (const int*)d_in[2];
    a.dst[1] = (const int*)d_in[3];
    a.dst[2] = (const int*)d_in[4];
    a.dst[3] = (const int*)d_in[5];

    const float* W1 = (const float*)d_in[18];
    const float* b1 = (const float*)d_in[19];
    const float* al = (const float*)d_in[20];
    const float* W2 = (const float*)d_in[21];
    const float* b2 = (const float*)d_in[22];
    float* out = (float*)d_out;

    dim3 tg((NNODE + 127) / 128, 2);
    transform_kernel<<<tg, 512>>>(t);

    dim3 ag((NNODE + 7) / 8, 4);
    agg_kernel<<<ag, 256>>>(a);

    dim3 ug((2 * NNODE + 127) / 128);
    update_kernel<<<ug, 256>>>(fa, fb, W1, b1, al, W2, b2, out);
}

// round 15
// speedup vs baseline: 1.0716x; 1.0716x over previous
#include <cuda_runtime.h>
#include <cuda_fp16.h>
#include <math.h>

#define NNODE 50000
#define EMB 35
#define DEG 32
#define NBH 40     // halves per feature row: 35 ch + s_b_even + s_b_odd + 3 pad = 80B (3 sectors)
#define MSTR 36    // g_m row stride (floats)

typedef unsigned long long ull;

// ---------------- scratch (device globals; no runtime allocation) ----------------
__device__ __half g_f16[2][NNODE * NBH];   // fp16 raw feature rows; side 0 = fa, 1 = fb
__device__ float  g_sa[4][NNODE];          // src-side attention score
__device__ float  g_m [4][NNODE * MSTR];   // aggregation results (raw-feature space)
__device__ float  g_W1f[2][105 * 72];      // per-side fused W1 (padded cols)
__device__ float  g_b1f[2][72];            // per-side fused bias
__device__ float  g_v[4][36];              // v_j = W_j @ att_hi (padded)
__device__ float  g_c[4];                  // c_j = b_j . att_hi

// ---------------- packed f32x2 helpers ----------------
static __device__ __forceinline__ ull pack2(float a, float b) {
    ull r;
    unsigned int lo = __float_as_uint(a), hi = __float_as_uint(b);
    asm("mov.b64 %0, {%1, %2};" : "=l"(r) : "r"(lo), "r"(hi));
    return r;
}
static __device__ __forceinline__ void unpack2(ull v, float &a, float &b) {
    unsigned int lo, hi;
    asm("mov.b64 {%0, %1}, %2;" : "=r"(lo), "=r"(hi) : "l"(v));
    a = __uint_as_float(lo);
    b = __uint_as_float(hi);
}
#define FMA2(d, a, b, c) \
    asm("fma.rn.f32x2 %0, %1, %2, %3;" : "=l"(d) : "l"(a), "l"(b), "l"(c))

// ---------------- kernel args ----------------
struct FArgs {
    const float* W[4];
    const float* b[4];
    const float* att[4];
    const float* W1;
    const float* b1;
};
struct CArgs {
    const float* fa;
    const float* fb;
    const float* att[4];
};
struct AArgs {
    const int* dst[4];
};

// =====================================================================
// Kernel 0 (R10, verbatim): fuse. Per side s (block): jobs j0=2s, j0+1.
//   g_W1f[s] rows 0-34 = W1[0:35]; rows 35+r = W_j @ W1-block (fused)
//   g_b1f[s] = b1 + b_j0@W1[35:70] + b_j1@W1[70:105]
//   g_v[j] = W_j @ att_j_hi ; g_c[j] = b_j . att_j_hi
// =====================================================================
__global__ __launch_bounds__(256) void fuse_kernel(FArgs f) {
    const int s  = blockIdx.x;
    const int j0 = 2 * s;

    __shared__ float Wj[2][35 * 36];   // 10080B
    __shared__ float W1b[70 * 72];     // 20160B

    const int tid = threadIdx.x;
    for (int i = tid; i < 2 * 35 * 36; i += 256) {
        int p = i / (35 * 36), r = i % (35 * 36);
        int k = r / 36, c = r % 36;
        Wj[p][r] = (c < EMB) ? f.W[j0 + p][k * EMB + c] : 0.0f;
    }
    for (int i = tid; i < 70 * 72; i += 256) {
        int r = i / 72, c = i % 72;
        W1b[i] = (c < 70) ? f.W1[(35 + r) * 70 + c] : 0.0f;
    }
    __syncthreads();

    for (int i = tid; i < 35 * 72; i += 256) {
        int g = i / 72, c = i % 72;
        g_W1f[s][i] = (c < 70) ? f.W1[g * 70 + c] : 0.0f;
    }
    for (int i = tid; i < 70 * 70; i += 256) {
        int r = i / 70, c = i % 70;
        int p = r / 35, k = r % 35;
        float acc = 0.0f;
        const float* wrow = &Wj[p][k * 36];
        const float* w1c  = &W1b[(35 * p) * 72 + c];
#pragma unroll 7
        for (int j = 0; j < 35; j++) acc = fmaf(wrow[j], w1c[j * 72], acc);
        g_W1f[s][(35 + r) * 72 + c] = acc;
    }
    for (int i = tid; i < 70 * 2; i += 256)
        g_W1f[s][(35 + i / 2) * 72 + 70 + (i & 1)] = 0.0f;

    for (int c = tid; c < 72; c += 256) {
        if (c < 70) {
            float a = f.b1[c];
            for (int j = 0; j < EMB; j++) a = fmaf(f.b[j0][j],     W1b[j * 72 + c],        a);
            for (int j = 0; j < EMB; j++) a = fmaf(f.b[j0 + 1][j], W1b[(35 + j) * 72 + c], a);
            g_b1f[s][c] = a;
        } else {
            g_b1f[s][c] = 0.0f;
        }
    }

    if (tid < 72) {
        int p = tid / 36, k = tid % 36;
        int j = j0 + p;
        float a = 0.0f;
        if (k < EMB) {
            const float* ah = f.att[j] + EMB;
#pragma unroll 7
            for (int c = 0; c < EMB; c++) a = fmaf(Wj[p][k * 36 + c], ah[c], a);
        }
        g_v[j][k] = a;
    }
    if (tid >= 72 && tid < 74) {
        int j = j0 + (tid - 72);
        float a = 0.0f;
        for (int c = 0; c < EMB; c++) a = fmaf(f.b[j][c], f.att[j][EMB + c], a);
        g_c[j] = a;
    }
}

// =====================================================================
// Kernel 1 (R10, verbatim): cast + scores. Side s: farr = (s ? fb : fa).
// =====================================================================
__global__ __launch_bounds__(256) void cast_kernel(CArgs a) {
    const int s   = blockIdx.y;
    const int jb0 = s ? 0 : 2;    // s_b jobs (fsrc == farr)
    const int ja0 = s ? 2 : 0;    // s_a jobs (fdst == farr)
    const float* __restrict__ farr = s ? a.fb : a.fa;

    __shared__ __align__(16) float Xs[128 * 37];
    __shared__ float vsh[2][36];
    __shared__ float ash[2][36];
    __shared__ float csh[2];

    const int tid = threadIdx.x;
    if (tid < 72) {
        int p = tid / 36, k = tid % 36;
        vsh[p][k] = g_v[jb0 + p][k];
        ash[p][k] = (k < EMB) ? a.att[ja0 + p][k] : 0.0f;
    }
    if (tid < 2) csh[tid] = g_c[jb0 + tid];

    const int base  = blockIdx.x * 128;
    const int nrows = min(128, NNODE - base);
    const int total = nrows * EMB;
    {
        const float* __restrict__ src = farr + base * EMB;
        for (int g = tid; g < total; g += 256)
            Xs[(g / EMB) * 37 + (g % EMB)] = src[g];
    }
    __syncthreads();

    const int row_l = tid >> 1;
    const int half  = tid & 1;
    const bool valid = (row_l < nrows);
    const int rl = valid ? row_l : 0;
    const int row = base + rl;
    const float* xrs = Xs + rl * 37;

    float sbe = 0.0f, sbo = 0.0f;
    if (half == 0) {
        float s0 = 0.0f, s1 = 0.0f;
#pragma unroll 7
        for (int k = 0; k < EMB; k++) {
            float xv = xrs[k];
            s0 = fmaf(xv, ash[0][k], s0);
            s1 = fmaf(xv, ash[1][k], s1);
        }
        if (valid) {
            g_sa[ja0][row]     = s0;
            g_sa[ja0 + 1][row] = s1;
        }
    } else {
        sbe = csh[0];
        sbo = csh[1];
#pragma unroll 7
        for (int k = 0; k < EMB; k++) {
            float xv = xrs[k];
            sbe = fmaf(xv, vsh[0][k], sbe);
            sbo = fmaf(xv, vsh[1][k], sbo);
        }
    }

    if (valid) {
        unsigned int* r =
            reinterpret_cast<unsigned int*>(&g_f16[s][row * NBH]) + 10 * half;
#pragma unroll
        for (int i = 0; i < 10; i++) {
            int i0 = 20 * half + 2 * i;
            float f0, f1;
            f0 = (i0 < EMB) ? xrs[i0] : ((i0 == 35) ? sbe : ((i0 == 36) ? sbo : 0.0f));
            int i1 = i0 + 1;
            f1 = (i1 < EMB) ? xrs[i1] : ((i1 == 35) ? sbe : ((i1 == 36) ? sbo : 0.0f));
            __half2 h = __floats2half2_rn(f0, f1);
            r[i] = *reinterpret_cast<unsigned int*>(&h);
        }
    }
}

// =====================================================================
// Kernel 2 (R10, verbatim): aggregation over RAW fp16 features.
// Row = 10 ull (80B, 3 sectors). s_b at slot 35 + (jid&1).
// =====================================================================
__global__ __launch_bounds__(256) void agg_kernel(AArgs args) {
    const int jid = blockIdx.y;
    const __half* __restrict__ nbh16 = g_f16[(jid < 2) ? 1 : 0];
    const ull* __restrict__ nb = reinterpret_cast<const ull*>(nbh16);
    const float* __restrict__ sav = g_sa[jid];
    const int*   __restrict__ dst = args.dst[jid];
    float* __restrict__ m = g_m[jid];
    const int parity = jid & 1;

    __shared__ float sw[8][36];
    __shared__ int   soff[8][36];

    const int wid  = threadIdx.x >> 5;
    const int lane = threadIdx.x & 31;
    const int node = blockIdx.x * 8 + wid;
    if (node >= NNODE) return;

    const int d = dst[node * DEG + lane];
    float sb = __half2float(nbh16[d * NBH + 35 + parity]);
    float x = sav[node] + sb;
    float e = (x > 0.0f) ? x : 0.1f * expm1f(x);   // elu(alpha=0.1)
    float w = expf(e);

    float wsum = w;
#pragma unroll
    for (int o = 16; o; o >>= 1) wsum += __shfl_xor_sync(0xffffffffu, wsum, o);

    sw[wid][lane]   = w;
    soff[wid][lane] = d * 10;
    if (lane == 0) { sw[wid][32] = 0.0f; soff[wid][32] = 0; }
    __syncwarp();

    const int sub   = (lane < 27) ? (lane / 9) : 2;
    const int piece = (lane < 27) ? (lane % 9) : (lane - 27);

    float a0 = 0.0f, a1 = 0.0f, a2 = 0.0f, a3 = 0.0f;
#pragma unroll
    for (int it = 0; it < 11; it++) {
        int j = it * 3 + sub;
        float wj = sw[wid][j];
        ull v = nb[soff[wid][j] + piece];
        unsigned int lo, hi;
        asm("mov.b64 {%0, %1}, %2;" : "=r"(lo), "=r"(hi) : "l"(v));
        float2 f0 = __half22float2(*reinterpret_cast<__half2*>(&lo));
        float2 f1 = __half22float2(*reinterpret_cast<__half2*>(&hi));
        a0 = fmaf(wj, f0.x, a0);
        a1 = fmaf(wj, f0.y, a1);
        a2 = fmaf(wj, f1.x, a2);
        a3 = fmaf(wj, f1.y, a3);
    }

    {
        float t, u;
        t = __shfl_down_sync(0xffffffffu, a0, 9);
        u = __shfl_down_sync(0xffffffffu, a0, 18);
        a0 += t + u;
        t = __shfl_down_sync(0xffffffffu, a1, 9);
        u = __shfl_down_sync(0xffffffffu, a1, 18);
        a1 += t + u;
        t = __shfl_down_sync(0xffffffffu, a2, 9);
        u = __shfl_down_sync(0xffffffffu, a2, 18);
        a2 += t + u;
        t = __shfl_down_sync(0xffffffffu, a3, 9);
        u = __shfl_down_sync(0xffffffffu, a3, 18);
        a3 += t + u;
    }

    if (lane < 9) {
        float inv = 1.0f / wsum;
        float4 o = make_float4(a0 * inv, a1 * inv, a2 * inv, a3 * inv);
        *reinterpret_cast<float4*>(m + node * MSTR + 4 * lane) = o;
    }
}

// =====================================================================
// Kernel 3: register-tiled update (R13 structure) with fused per-side
// W1f/b1f. gridDim.y = side. fp16 X/H staging, LDS.128 W reads.
// =====================================================================
__global__ __launch_bounds__(256, 3) void update_kernel(
    const float* __restrict__ fa, const float* __restrict__ fb,
    const float* __restrict__ alpha_p,
    const float* __restrict__ W2, const float* __restrict__ b2,
    float* __restrict__ out)
{
    const int side = blockIdx.y;

    __shared__ __align__(16) __half Xh[105 * 132];  // 27720B: Xh, then Hh
    __shared__ __align__(16) ull   w1p[105 * 40];   // 33600B padded packed W1f
    __shared__ __align__(16) ull   w2p[70 * 20];    // 11200B padded packed W2
    __shared__ __align__(16) ull   b1p[36];
    __shared__ __align__(16) ull   b2p[18];

    const int tid = threadIdx.x;
    {
        const float* __restrict__ src = g_W1f[side];
        for (int i = tid; i < 105 * 36; i += 256) {
            int k = i / 36, j = i % 36;
            w1p[k * 40 + j + j / 9] = pack2(src[k * 72 + 2 * j], src[k * 72 + 2 * j + 1]);
        }
    }
    for (int i = tid; i < 70 * 18; i += 256) {
        int k = i / 18, p = i % 18;
        int c = 2 * p;
        int slot = p + (p >= 5 ? 1 : 0) + (p >= 10 ? 1 : 0);
        w2p[k * 20 + slot] =
            pack2(W2[k * EMB + c], (c + 1 < EMB) ? W2[k * EMB + c + 1] : 0.0f);
    }
    if (tid < 36) b1p[tid] = pack2(g_b1f[side][2 * tid], g_b1f[side][2 * tid + 1]);
    if (tid < 18) {
        int c = 2 * tid;
        b2p[tid] = pack2(b2[c], (c + 1 < EMB) ? b2[c + 1] : 0.0f);
    }

    const int base = blockIdx.x * 128;
    const float* __restrict__ feat = side ? fb : fa;
    const float* __restrict__ m0 = g_m[2 * side];
    const float* __restrict__ m1 = g_m[2 * side + 1];

    // ---- stage X transposed as fp16: Xh[k*132 + node_l] ----
    for (int g = tid; g < 128 * 105; g += 256) {
        int nl = g / 105;
        int k  = g - nl * 105;
        int n  = base + nl;
        float v = 0.0f;
        if (n < NNODE) {
            if (k < EMB)          v = feat[n * EMB + k];
            else if (k < 2 * EMB) v = m0[n * MSTR + (k - EMB)];
            else                  v = m1[n * MSTR + (k - 2 * EMB)];
        }
        Xh[k * 132 + nl] = __float2half_rn(v);
    }
    __syncthreads();

    const int cg = tid >> 6;
    const int ng = tid & 63;
    const int n0 = base + 2 * ng;
    const float alpha = __ldg(alpha_p);

    // ---- GEMM1: 2 nodes x 9 pairs ----
    ull acc0[9], acc1[9];
#pragma unroll
    for (int i = 0; i < 9; i++) { acc0[i] = b1p[9 * cg + i]; acc1[i] = acc0[i]; }

    const ull* wbase = w1p + 10 * cg;
    for (int k = 0; k < 105; k++) {
        __half2 hv = *reinterpret_cast<const __half2*>(&Xh[k * 132 + 2 * ng]);
        float2 xv = __half22float2(hv);
        ull xx0 = pack2(xv.x, xv.x);
        ull xx1 = pack2(xv.y, xv.y);
        const ull* wr = wbase + k * 40;
        const ulonglong2* wv2 = reinterpret_cast<const ulonglong2*>(wr);
#pragma unroll
        for (int i = 0; i < 4; i++) {
            ulonglong2 wv = wv2[i];
            FMA2(acc0[2 * i],     wv.x, xx0, acc0[2 * i]);
            FMA2(acc1[2 * i],     wv.x, xx1, acc1[2 * i]);
            FMA2(acc0[2 * i + 1], wv.y, xx0, acc0[2 * i + 1]);
            FMA2(acc1[2 * i + 1], wv.y, xx1, acc1[2 * i + 1]);
        }
        {
            ull w = wr[8];
            FMA2(acc0[8], w, xx0, acc0[8]);
            FMA2(acc1[8], w, xx1, acc1[8]);
        }
    }
    __syncthreads();   // Xh reads complete; buffer becomes Hh

    // ---- PReLU, publish Hh ----
#pragma unroll
    for (int i = 0; i < 9; i++) {
        int c = 18 * cg + 2 * i;
        float h0, h1, g0, g1;
        unpack2(acc0[i], h0, h1);
        unpack2(acc1[i], g0, g1);
        h0 = (h0 > 0.0f) ? h0 : alpha * h0;
        h1 = (h1 > 0.0f) ? h1 : alpha * h1;
        g0 = (g0 > 0.0f) ? g0 : alpha * g0;
        g1 = (g1 > 0.0f) ? g1 : alpha * g1;
        __half2 p0 = __floats2half2_rn(h0, g0);
        __half2 p1 = __floats2half2_rn(h1, g1);
        *reinterpret_cast<__half2*>(&Xh[c * 132 + 2 * ng])       = p0;
        *reinterpret_cast<__half2*>(&Xh[(c + 1) * 132 + 2 * ng]) = p1;
    }
    __syncthreads();

    // ---- GEMM2 ----
    const int p0 = (cg < 2) ? cg * 5 : 10 + (cg - 2) * 4;
    const int np = (cg < 2) ? 5 : 4;
    const int soff = (cg < 2) ? cg * 6 : 12 + (cg - 2) * 4;

    ull a20[5], a21[5];
#pragma unroll
    for (int q = 0; q < 5; q++) {
        ull b = (q < np) ? b2p[p0 + q] : 0ull;
        a20[q] = b;
        a21[q] = b;
    }

    const ull* w2base = w2p + soff;
    for (int k = 0; k < 70; k++) {
        __half2 hv = *reinterpret_cast<const __half2*>(&Xh[k * 132 + 2 * ng]);
        float2 xv = __half22float2(hv);
        ull xx0 = pack2(xv.x, xv.x);
        ull xx1 = pack2(xv.y, xv.y);
        const ull* wr = w2base + k * 20;
        const ulonglong2* wv2 = reinterpret_cast<const ulonglong2*>(wr);
#pragma unroll
        for (int i = 0; i < 2; i++) {
            ulonglong2 wv = wv2[i];
            FMA2(a20[2 * i],     wv.x, xx0, a20[2 * i]);
            FMA2(a21[2 * i],     wv.x, xx1, a21[2 * i]);
            FMA2(a20[2 * i + 1], wv.y, xx0, a20[2 * i + 1]);
            FMA2(a21[2 * i + 1], wv.y, xx1, a21[2 * i + 1]);
        }
        if (np == 5) {
            ull w = wr[4];
            FMA2(a20[4], w, xx0, a20[4]);
            FMA2(a21[4], w, xx1, a21[4]);
        }
    }

#pragma unroll
    for (int p = 0; p < 2; p++) {
        int n = n0 + p;
        if (n < NNODE) {
            float* orow = out + (side * NNODE + n) * EMB;
#pragma unroll
            for (int q = 0; q < 5; q++) {
                if (q < np) {
                    float v0, v1;
                    unpack2(p ? a21[q] : a20[q], v0, v1);
                    int c = 2 * (p0 + q);
                    orow[c] = v0;
                    if (c + 1 < EMB) orow[c + 1] = v1;
                }
            }
        }
    }
}

// =====================================================================
// launch
// =====================================================================
extern "C" void kernel_launch(void* const* d_in, const int* in_sizes, int n_in,
                              void* d_out, int out_size) {
    const float* fa = (const float*)d_in[0];
    const float* fb = (const float*)d_in[1];

    FArgs f;
    for (int j = 0; j < 4; j++) {
        f.W[j]   = (const float*)d_in[6 + 3 * j];
        f.b[j]   = (const float*)d_in[7 + 3 * j];
        f.att[j] = (const float*)d_in[8 + 3 * j];
    }
    f.W1 = (const float*)d_in[18];
    f.b1 = (const float*)d_in[19];

    CArgs c;
    c.fa = fa;
    c.fb = fb;
    for (int j = 0; j < 4; j++) c.att[j] = f.att[j];

    AArgs a;
    a.dst[0] = (const int*)d_in[2];
    a.dst[1] = (const int*)d_in[3];
    a.dst[2] = (const int*)d_in[4];
    a.dst[3] = (const int*)d_in[5];

    const float* al = (const float*)d_in[20];
    const float* W2 = (const float*)d_in[21];
    const float* b2 = (const float*)d_in[22];
    float* out = (float*)d_out;

    fuse_kernel<<<2, 256>>>(f);

    dim3 cg((NNODE + 127) / 128, 2);
    cast_kernel<<<cg, 256>>>(c);

    dim3 ag((NNODE + 7) / 8, 4);
    agg_kernel<<<ag, 256>>>(a);

    dim3 ug((NNODE + 127) / 128, 2);
    update_kernel<<<ug, 256>>>(fa, fb, al, W2, b2, out);
}

// round 16
// speedup vs baseline: 1.3655x; 1.2743x over previous
#include <cuda_runtime.h>
#include <cuda_fp16.h>
#include <math.h>

#define NNODE 50000
#define EMB 35
#define DEG 32
#define NBH 40     // halves per feature row: 35 ch + s_b_even + s_b_odd + pad = 80B (3 sectors)
#define MSTR 36    // g_m row stride (floats)

typedef unsigned long long ull;
typedef unsigned int uint;

// ---------------- scratch (device globals; no runtime allocation) ----------------
__device__ __half g_f16[2][NNODE * NBH];   // fp16 raw feature rows; side 0 = fa, 1 = fb
__device__ float  g_sa[4][NNODE];          // src-side attention score
__device__ float  g_m [4][NNODE * MSTR];   // aggregation results (raw-feature space)
__device__ __half g_W1fT[2][80 * 120];     // per-side fused W1, TRANSPOSED [n][k], fp16
__device__ float  g_b1f[2][80];            // per-side fused bias (padded)
__device__ __half g_W2T[40 * 88];          // W2 transposed [n][k], fp16, padded
__device__ float  g_v[4][36];              // v_j = W_j @ att_hi (padded)
__device__ float  g_c[4];                  // c_j = b_j . att_hi

// ---------------- helpers ----------------
static __device__ __forceinline__ uint h2u(float a, float b) {
    __half2 h = __floats2half2_rn(a, b);
    return *reinterpret_cast<uint*>(&h);
}
#define MMA16816(d, a0, a1, a2, a3, b0, b1)                              \
    asm volatile(                                                        \
        "mma.sync.aligned.m16n8k16.row.col.f32.f16.f16.f32 "            \
        "{%0,%1,%2,%3}, {%4,%5,%6,%7}, {%8,%9}, {%0,%1,%2,%3};"         \
        : "+f"(d[0]), "+f"(d[1]), "+f"(d[2]), "+f"(d[3])                 \
        : "r"(a0), "r"(a1), "r"(a2), "r"(a3), "r"(b0), "r"(b1))

// ---------------- kernel args ----------------
struct FArgs {
    const float* W[4];
    const float* b[4];
    const float* att[4];
    const float* W1;
    const float* b1;
    const float* W2;
};
struct CArgs {
    const float* fa;
    const float* fb;
    const float* att[4];
};
struct AArgs {
    const int* dst[4];
};

// =====================================================================
// Kernel 0: fuse. Per side s (block): jobs j0=2s, j0+1.
//   g_W1fT[s][n][k] (fp16): k<35 -> W1[k][n]; 35<=k<105 -> (W_j @ W1-block)[k-35][n]
//   g_b1f[s] = b1 + b_j0@W1[35:70] + b_j1@W1[70:105]  (fp32)
//   g_W2T[n][k] = W2[k][n] (fp16, block s==0 only)
//   g_v[j] = W_j @ att_j_hi ; g_c[j] = b_j . att_j_hi
// =====================================================================
__global__ __launch_bounds__(256) void fuse_kernel(FArgs f) {
    const int s  = blockIdx.x;
    const int j0 = 2 * s;

    __shared__ float Wj[2][35 * 36];   // 10080B
    __shared__ float W1b[70 * 72];     // 20160B (W1 rows 35..104, padded)

    const int tid = threadIdx.x;
    for (int i = tid; i < 2 * 35 * 36; i += 256) {
        int p = i / (35 * 36), r = i % (35 * 36);
        int k = r / 36, c = r % 36;
        Wj[p][r] = (c < EMB) ? f.W[j0 + p][k * EMB + c] : 0.0f;
    }
    for (int i = tid; i < 70 * 72; i += 256) {
        int r = i / 72, c = i % 72;
        W1b[i] = (c < 70) ? f.W1[(35 + r) * 70 + c] : 0.0f;
    }
    // zero-fill fp16 targets (ordering vs fills enforced by the barrier below)
    {
        __half z = __float2half(0.0f);
        for (int i = tid; i < 80 * 120; i += 256) g_W1fT[s][i] = z;
        if (s == 0)
            for (int i = tid; i < 40 * 88; i += 256) g_W2T[i] = z;
    }
    __syncthreads();

    // W1fT rows 0-34 of k: direct copy of W1 (transposed)
    for (int i = tid; i < 35 * 70; i += 256) {
        int k = i / 70, c = i % 70;
        g_W1fT[s][c * 120 + k] = __float2half(f.W1[k * 70 + c]);
    }
    // fused k rows 35..104
    for (int i = tid; i < 70 * 70; i += 256) {
        int r = i / 70, c = i % 70;
        int p = r / 35, k = r % 35;
        float acc = 0.0f;
        const float* wrow = &Wj[p][k * 36];
        const float* w1c  = &W1b[(35 * p) * 72 + c];
#pragma unroll 7
        for (int j = 0; j < 35; j++) acc = fmaf(wrow[j], w1c[j * 72], acc);
        g_W1fT[s][c * 120 + 35 + r] = __float2half(acc);
    }
    // fused bias (fp32)
    for (int c = tid; c < 80; c += 256) {
        float a = 0.0f;
        if (c < 70) {
            a = f.b1[c];
            for (int j = 0; j < EMB; j++) a = fmaf(f.b[j0][j],     W1b[j * 72 + c],        a);
            for (int j = 0; j < EMB; j++) a = fmaf(f.b[j0 + 1][j], W1b[(35 + j) * 72 + c], a);
        }
        g_b1f[s][c] = a;
    }
    // W2T (block 0 only)
    if (s == 0) {
        for (int i = tid; i < 70 * 35; i += 256) {
            int k = i / 35, n = i % 35;
            g_W2T[n * 88 + k] = __float2half(f.W2[k * EMB + n]);
        }
    }
    // v_j and c_j
    if (tid < 72) {
        int p = tid / 36, k = tid % 36;
        int j = j0 + p;
        float a = 0.0f;
        if (k < EMB) {
            const float* ah = f.att[j] + EMB;
#pragma unroll 7
            for (int c = 0; c < EMB; c++) a = fmaf(Wj[p][k * 36 + c], ah[c], a);
        }
        g_v[j][k] = a;
    }
    if (tid >= 72 && tid < 74) {
        int j = j0 + (tid - 72);
        float a = 0.0f;
        for (int c = 0; c < EMB; c++) a = fmaf(f.b[j][c], f.att[j][EMB + c], a);
        g_c[j] = a;
    }
}

// =====================================================================
// Kernel 1 (passing R15, verbatim): cast + scores.
// =====================================================================
__global__ __launch_bounds__(256) void cast_kernel(CArgs a) {
    const int s   = blockIdx.y;
    const int jb0 = s ? 0 : 2;
    const int ja0 = s ? 2 : 0;
    const float* __restrict__ farr = s ? a.fb : a.fa;

    __shared__ __align__(16) float Xs[128 * 37];
    __shared__ float vsh[2][36];
    __shared__ float ash[2][36];
    __shared__ float csh[2];

    const int tid = threadIdx.x;
    if (tid < 72) {
        int p = tid / 36, k = tid % 36;
        vsh[p][k] = g_v[jb0 + p][k];
        ash[p][k] = (k < EMB) ? a.att[ja0 + p][k] : 0.0f;
    }
    if (tid < 2) csh[tid] = g_c[jb0 + tid];

    const int base  = blockIdx.x * 128;
    const int nrows = min(128, NNODE - base);
    const int total = nrows * EMB;
    {
        const float* __restrict__ src = farr + base * EMB;
        for (int g = tid; g < total; g += 256)
            Xs[(g / EMB) * 37 + (g % EMB)] = src[g];
    }
    __syncthreads();

    const int row_l = tid >> 1;
    const int half  = tid & 1;
    const bool valid = (row_l < nrows);
    const int rl = valid ? row_l : 0;
    const int row = base + rl;
    const float* xrs = Xs + rl * 37;

    float sbe = 0.0f, sbo = 0.0f;
    if (half == 0) {
        float s0 = 0.0f, s1 = 0.0f;
#pragma unroll 7
        for (int k = 0; k < EMB; k++) {
            float xv = xrs[k];
            s0 = fmaf(xv, ash[0][k], s0);
            s1 = fmaf(xv, ash[1][k], s1);
        }
        if (valid) {
            g_sa[ja0][row]     = s0;
            g_sa[ja0 + 1][row] = s1;
        }
    } else {
        sbe = csh[0];
        sbo = csh[1];
#pragma unroll 7
        for (int k = 0; k < EMB; k++) {
            float xv = xrs[k];
            sbe = fmaf(xv, vsh[0][k], sbe);
            sbo = fmaf(xv, vsh[1][k], sbo);
        }
    }

    if (valid) {
        uint* r = reinterpret_cast<uint*>(&g_f16[s][row * NBH]) + 10 * half;
#pragma unroll
        for (int i = 0; i < 10; i++) {
            int i0 = 20 * half + 2 * i;
            float f0, f1;
            f0 = (i0 < EMB) ? xrs[i0] : ((i0 == 35) ? sbe : ((i0 == 36) ? sbo : 0.0f));
            int i1 = i0 + 1;
            f1 = (i1 < EMB) ? xrs[i1] : ((i1 == 35) ? sbe : ((i1 == 36) ? sbo : 0.0f));
            r[i] = h2u(f0, f1);
        }
    }
}

// =====================================================================
// Kernel 2 (passing R15, verbatim): aggregation over RAW fp16 features.
// =====================================================================
__global__ __launch_bounds__(256) void agg_kernel(AArgs args) {
    const int jid = blockIdx.y;
    const __half* __restrict__ nbh16 = g_f16[(jid < 2) ? 1 : 0];
    const ull* __restrict__ nb = reinterpret_cast<const ull*>(nbh16);
    const float* __restrict__ sav = g_sa[jid];
    const int*   __restrict__ dst = args.dst[jid];
    float* __restrict__ m = g_m[jid];
    const int parity = jid & 1;

    __shared__ float sw[8][36];
    __shared__ int   soff[8][36];

    const int wid  = threadIdx.x >> 5;
    const int lane = threadIdx.x & 31;
    const int node = blockIdx.x * 8 + wid;
    if (node >= NNODE) return;

    const int d = dst[node * DEG + lane];
    float sb = __half2float(nbh16[d * NBH + 35 + parity]);
    float x = sav[node] + sb;
    float e = (x > 0.0f) ? x : 0.1f * expm1f(x);   // elu(alpha=0.1)
    float w = expf(e);

    float wsum = w;
#pragma unroll
    for (int o = 16; o; o >>= 1) wsum += __shfl_xor_sync(0xffffffffu, wsum, o);

    sw[wid][lane]   = w;
    soff[wid][lane] = d * 10;
    if (lane == 0) { sw[wid][32] = 0.0f; soff[wid][32] = 0; }
    __syncwarp();

    const int sub   = (lane < 27) ? (lane / 9) : 2;
    const int piece = (lane < 27) ? (lane % 9) : (lane - 27);

    float a0 = 0.0f, a1 = 0.0f, a2 = 0.0f, a3 = 0.0f;
#pragma unroll
    for (int it = 0; it < 11; it++) {
        int j = it * 3 + sub;
        float wj = sw[wid][j];
        ull v = nb[soff[wid][j] + piece];
        uint lo, hi;
        asm("mov.b64 {%0, %1}, %2;" : "=r"(lo), "=r"(hi) : "l"(v));
        float2 f0 = __half22float2(*reinterpret_cast<__half2*>(&lo));
        float2 f1 = __half22float2(*reinterpret_cast<__half2*>(&hi));
        a0 = fmaf(wj, f0.x, a0);
        a1 = fmaf(wj, f0.y, a1);
        a2 = fmaf(wj, f1.x, a2);
        a3 = fmaf(wj, f1.y, a3);
    }

    {
        float t, u;
        t = __shfl_down_sync(0xffffffffu, a0, 9);
        u = __shfl_down_sync(0xffffffffu, a0, 18);
        a0 += t + u;
        t = __shfl_down_sync(0xffffffffu, a1, 9);
        u = __shfl_down_sync(0xffffffffu, a1, 18);
        a1 += t + u;
        t = __shfl_down_sync(0xffffffffu, a2, 9);
        u = __shfl_down_sync(0xffffffffu, a2, 18);
        a2 += t + u;
        t = __shfl_down_sync(0xffffffffu, a3, 9);
        u = __shfl_down_sync(0xffffffffu, a3, 18);
        a3 += t + u;
    }

    if (lane < 9) {
        float inv = 1.0f / wsum;
        float4 o = make_float4(a0 * inv, a1 * inv, a2 * inv, a3 * inv);
        *reinterpret_cast<float4*>(m + node * MSTR + 4 * lane) = o;
    }
}

// =====================================================================
// Kernel 3 (NEW): tensor-core update via mma.sync.m16n8k16 (f16 in, f32 acc).
// Block = 128 nodes, 8 warps; warp owns 16 M-rows.
// GEMM1: [128 x 112] @ W1fT^T -> [128 x 80]; PReLU in fragments;
// H fp16 -> smem (reusing X buffer); GEMM2: [128 x 80] @ W2T^T -> [128 x 40].
// Direct fragment stores to out. gridDim.y = side.
// =====================================================================
__global__ __launch_bounds__(256) void update_kernel(
    const float* __restrict__ fa, const float* __restrict__ fb,
    const float* __restrict__ alpha_p,
    const float* __restrict__ b2,
    float* __restrict__ out)
{
    const int side = blockIdx.y;

    __shared__ __align__(16) __half Xh[128 * 120];  // 30720B; reused as H[128*88]
    __shared__ __align__(16) __half W1T[80 * 120];  // 19200B
    __shared__ __align__(16) __half W2T[40 * 88];   // 7040B

    const int tid = threadIdx.x;

    // ---- stage weights (ull copies) ----
    {
        const ull* src = reinterpret_cast<const ull*>(g_W1fT[side]);
        ull* dst = reinterpret_cast<ull*>(W1T);
        for (int i = tid; i < 80 * 120 / 4; i += 256) dst[i] = src[i];
        const ull* s2 = reinterpret_cast<const ull*>(g_W2T);
        ull* d2 = reinterpret_cast<ull*>(W2T);
        for (int i = tid; i < 40 * 88 / 4; i += 256) d2[i] = s2[i];
    }

    // ---- stage X fp16: Xh[node][k], stride 120 halves ----
    const int base = blockIdx.x * 128;
    const float* __restrict__ feat = side ? fb : fa;
    const float* __restrict__ m0 = g_m[2 * side];
    const float* __restrict__ m1 = g_m[2 * side + 1];

    uint* Xu = reinterpret_cast<uint*>(Xh);
    for (int p = tid; p < 128 * 60; p += 256) {
        int nl = p / 60;
        int kp = p - nl * 60;
        int n = base + nl;
        float v0 = 0.0f, v1 = 0.0f;
        if (n < NNODE) {
            int k0 = 2 * kp;
#pragma unroll
            for (int t = 0; t < 2; t++) {
                int k = k0 + t;
                float v = 0.0f;
                if (k < EMB)          v = feat[n * EMB + k];
                else if (k < 2 * EMB) v = m0[n * MSTR + (k - EMB)];
                else if (k < 3 * EMB) v = m1[n * MSTR + (k - 2 * EMB)];
                if (t == 0) v0 = v; else v1 = v;
            }
        }
        Xu[nl * 60 + kp] = h2u(v0, v1);
    }
    __syncthreads();

    const int wid  = tid >> 5;
    const int lane = tid & 31;
    const int rg   = lane >> 2;     // group row 0..7
    const int cg   = lane & 3;      // group col 0..3
    const int m0r  = wid * 16;
    const float alpha = __ldg(alpha_p);

    // ---- GEMM1: C1[10 n-tiles][4], init with fused bias ----
    float c1[10][4];
#pragma unroll
    for (int j = 0; j < 10; j++) {
        int col = 8 * j + 2 * cg;
        float b0v = __ldg(&g_b1f[side][col]);
        float b1v = __ldg(&g_b1f[side][col + 1]);
        c1[j][0] = b0v; c1[j][1] = b1v; c1[j][2] = b0v; c1[j][3] = b1v;
    }

    const uint* W1u = reinterpret_cast<const uint*>(W1T);
#pragma unroll
    for (int ks = 0; ks < 7; ks++) {
        int ab = (m0r + rg) * 60 + 8 * ks + cg;
        uint a0 = Xu[ab];
        uint a1 = Xu[ab + 8 * 60];
        uint a2 = Xu[ab + 4];
        uint a3 = Xu[ab + 8 * 60 + 4];
#pragma unroll
        for (int j = 0; j < 10; j++) {
            int bb = (8 * j + rg) * 60 + 8 * ks + cg;
            uint b0 = W1u[bb];
            uint b1 = W1u[bb + 4];
            MMA16816(c1[j], a0, a1, a2, a3, b0, b1);
        }
    }
    __syncthreads();   // X reads done; buffer becomes H

    // ---- PReLU, store H fp16 (stride 88 halves = 44 uints) ----
    uint* Hu = reinterpret_cast<uint*>(Xh);
#pragma unroll
    for (int j = 0; j < 10; j++) {
        float h00 = c1[j][0], h01 = c1[j][1], h10 = c1[j][2], h11 = c1[j][3];
        h00 = (h00 > 0.0f) ? h00 : alpha * h00;
        h01 = (h01 > 0.0f) ? h01 : alpha * h01;
        h10 = (h10 > 0.0f) ? h10 : alpha * h10;
        h11 = (h11 > 0.0f) ? h11 : alpha * h11;
        Hu[(m0r + rg) * 44 + 4 * j + cg]       = h2u(h00, h01);
        Hu[(m0r + rg + 8) * 44 + 4 * j + cg]   = h2u(h10, h11);
    }
    __syncthreads();

    // ---- GEMM2: C2[5][4], init with b2 ----
    float c2[5][4];
#pragma unroll
    for (int j = 0; j < 5; j++) {
        int col = 8 * j + 2 * cg;
        float b0v = (col < EMB)     ? __ldg(&b2[col])     : 0.0f;
        float b1v = (col + 1 < EMB) ? __ldg(&b2[col + 1]) : 0.0f;
        c2[j][0] = b0v; c2[j][1] = b1v; c2[j][2] = b0v; c2[j][3] = b1v;
    }

    const uint* W2u = reinterpret_cast<const uint*>(W2T);
#pragma unroll
    for (int ks = 0; ks < 5; ks++) {
        int ab = (m0r + rg) * 44 + 8 * ks + cg;
        uint a0 = Hu[ab];
        uint a1 = Hu[ab + 8 * 44];
        uint a2 = Hu[ab + 4];
        uint a3 = Hu[ab + 8 * 44 + 4];
#pragma unroll
        for (int j = 0; j < 5; j++) {
            int bb = (8 * j + rg) * 44 + 8 * ks + cg;
            uint b0 = W2u[bb];
            uint b1 = W2u[bb + 4];
            MMA16816(c2[j], a0, a1, a2, a3, b0, b1);
        }
    }

    // ---- fragment stores to out ----
#pragma unroll
    for (int p = 0; p < 2; p++) {
        int row = m0r + rg + 8 * p;
        int n = base + row;
        if (n < NNODE) {
            float* orow = out + (side * NNODE + n) * EMB;
#pragma unroll
            for (int j = 0; j < 5; j++) {
                int col = 8 * j + 2 * cg;
                if (col < EMB)     orow[col]     = c2[j][2 * p];
                if (col + 1 < EMB) orow[col + 1] = c2[j][2 * p + 1];
            }
        }
    }
}

// =====================================================================
// launch
// =====================================================================
extern "C" void kernel_launch(void* const* d_in, const int* in_sizes, int n_in,
                              void* d_out, int out_size) {
    const float* fa = (const float*)d_in[0];
    const float* fb = (const float*)d_in[1];

    FArgs f;
    for (int j = 0; j < 4; j++) {
        f.W[j]   = (const float*)d_in[6 + 3 * j];
        f.b[j]   = (const float*)d_in[7 + 3 * j];
        f.att[j] = (const float*)d_in[8 + 3 * j];
    }
    f.W1 = (const float*)d_in[18];
    f.b1 = (const float*)d_in[19];
    f.W2 = (const float*)d_in[21];

    CArgs c;
    c.fa = fa;
    c.fb = fb;
    for (int j = 0; j < 4; j++) c.att[j] = f.att[j];

    AArgs a;
    a.dst[0] = (const int*)d_in[2];
    a.dst[1] = (const int*)d_in[3];
    a.dst[2] = (const int*)d_in[4];
    a.dst[3] = (const int*)d_in[5];

    const float* al = (const float*)d_in[20];
    const float* b2 = (const float*)d_in[22];
    float* out = (float*)d_out;

    fuse_kernel<<<2, 256>>>(f);

    dim3 cg((NNODE + 127) / 128, 2);
    cast_kernel<<<cg, 256>>>(c);

    dim3 ag((NNODE + 7) / 8, 4);
    agg_kernel<<<ag, 256>>>(a);

    dim3 ug((NNODE + 127) / 128, 2);
    update_kernel<<<ug, 256>>>(fa, fb, al, b2, out);
}

// round 17
// speedup vs baseline: 1.4695x; 1.0761x over previous
#include <cuda_runtime.h>
#include <cuda_fp16.h>
#include <math.h>

#define NNODE 50000
#define EMB 35
#define DEG 32
#define NBH 40     // halves per feature row: 35 ch + s_b_even + s_b_odd + pad = 80B (3 sectors)

typedef unsigned long long ull;
typedef unsigned int uint;

// ---------------- scratch (device globals; no runtime allocation) ----------------
__device__ __half g_f16[2][NNODE * NBH];   // fp16 raw feature rows; side 0 = fa, 1 = fb
__device__ float  g_sa[4][NNODE];          // src-side attention score
__device__ __half g_mh[4][NNODE * 40];     // aggregation results, fp16 rows (40 halves)
__device__ __half g_W1fT[2][80 * 112];     // per-side fused W1, transposed [n][k-padded], fp16
__device__ float  g_b1f[2][80];            // per-side fused bias (padded)
__device__ __half g_W2T[40 * 80];          // W2 transposed [n][k], fp16, padded
__device__ float  g_v[4][36];              // v_j = W_j @ att_hi (padded)
__device__ float  g_c[4];                  // c_j = b_j . att_hi

// ---------------- helpers ----------------
static __device__ __forceinline__ uint h2u(float a, float b) {
    __half2 h = __floats2half2_rn(a, b);
    return *reinterpret_cast<uint*>(&h);
}
#define MMA16816(d, a0, a1, a2, a3, b0, b1)                              \
    asm volatile(                                                        \
        "mma.sync.aligned.m16n8k16.row.col.f32.f16.f16.f32 "            \
        "{%0,%1,%2,%3}, {%4,%5,%6,%7}, {%8,%9}, {%0,%1,%2,%3};"         \
        : "+f"(d[0]), "+f"(d[1]), "+f"(d[2]), "+f"(d[3])                 \
        : "r"(a0), "r"(a1), "r"(a2), "r"(a3), "r"(b0), "r"(b1))

// ---------------- kernel args ----------------
struct FArgs {
    const float* W[4];
    const float* b[4];
    const float* att[4];
    const float* W1;
    const float* b1;
    const float* W2;
};
struct CArgs {
    const float* fa;
    const float* fb;
    const float* att[4];
};
struct AArgs {
    const int* dst[4];
};

// =====================================================================
// Kernel 0: fuse. Per side s (block): jobs j0=2s, j0+1.
// X k-layout (padded): feat k -> k (0..34), m0 r -> 36+r, m1 r -> 72+r;
// pad rows (35, 71, 107..111) stay zero so segment-copied garbage is inert.
//   g_W1fT[s][n][kx] fp16; g_b1f fp32; g_W2T[n][k] fp16 (s==0 only)
//   g_v[j] = W_j @ att_j_hi ; g_c[j] = b_j . att_j_hi
// =====================================================================
__global__ __launch_bounds__(256) void fuse_kernel(FArgs f) {
    const int s  = blockIdx.x;
    const int j0 = 2 * s;

    __shared__ float Wj[2][35 * 36];   // 10080B
    __shared__ float W1b[70 * 72];     // 20160B (W1 rows 35..104, padded)

    const int tid = threadIdx.x;
    for (int i = tid; i < 2 * 35 * 36; i += 256) {
        int p = i / (35 * 36), r = i % (35 * 36);
        int k = r / 36, c = r % 36;
        Wj[p][r] = (c < EMB) ? f.W[j0 + p][k * EMB + c] : 0.0f;
    }
    for (int i = tid; i < 70 * 72; i += 256) {
        int r = i / 72, c = i % 72;
        W1b[i] = (c < 70) ? f.W1[(35 + r) * 70 + c] : 0.0f;
    }
    // zero-fill fp16 targets
    {
        __half z = __float2half(0.0f);
        for (int i = tid; i < 80 * 112; i += 256) g_W1fT[s][i] = z;
        if (s == 0)
            for (int i = tid; i < 40 * 80; i += 256) g_W2T[i] = z;
    }
    __syncthreads();

    // k rows 0-34: direct copy of W1 (transposed)
    for (int i = tid; i < 35 * 70; i += 256) {
        int k = i / 70, c = i % 70;
        g_W1fT[s][c * 112 + k] = __float2half(f.W1[k * 70 + c]);
    }
    // fused k rows: m0 -> 36+k, m1 -> 72+k
    for (int i = tid; i < 70 * 70; i += 256) {
        int r = i / 70, c = i % 70;
        int p = r / 35, k = r % 35;
        float acc = 0.0f;
        const float* wrow = &Wj[p][k * 36];
        const float* w1c  = &W1b[(35 * p) * 72 + c];
#pragma unroll 7
        for (int j = 0; j < 35; j++) acc = fmaf(wrow[j], w1c[j * 72], acc);
        g_W1fT[s][c * 112 + 36 + 36 * p + k] = __float2half(acc);
    }
    // fused bias (fp32)
    for (int c = tid; c < 80; c += 256) {
        float a = 0.0f;
        if (c < 70) {
            a = f.b1[c];
            for (int j = 0; j < EMB; j++) a = fmaf(f.b[j0][j],     W1b[j * 72 + c],        a);
            for (int j = 0; j < EMB; j++) a = fmaf(f.b[j0 + 1][j], W1b[(35 + j) * 72 + c], a);
        }
        g_b1f[s][c] = a;
    }
    // W2T (block 0 only)
    if (s == 0) {
        for (int i = tid; i < 70 * 35; i += 256) {
            int k = i / 35, n = i % 35;
            g_W2T[n * 80 + k] = __float2half(f.W2[k * EMB + n]);
        }
    }
    // v_j and c_j
    if (tid < 72) {
        int p = tid / 36, k = tid % 36;
        int j = j0 + p;
        float a = 0.0f;
        if (k < EMB) {
            const float* ah = f.att[j] + EMB;
#pragma unroll 7
            for (int c = 0; c < EMB; c++) a = fmaf(Wj[p][k * 36 + c], ah[c], a);
        }
        g_v[j][k] = a;
    }
    if (tid >= 72 && tid < 74) {
        int j = j0 + (tid - 72);
        float a = 0.0f;
        for (int c = 0; c < EMB; c++) a = fmaf(f.b[j][c], f.att[j][EMB + c], a);
        g_c[j] = a;
    }
}

// =====================================================================
// Kernel 1 (passing R16, verbatim): cast + scores.
// =====================================================================
__global__ __launch_bounds__(256) void cast_kernel(CArgs a) {
    const int s   = blockIdx.y;
    const int jb0 = s ? 0 : 2;
    const int ja0 = s ? 2 : 0;
    const float* __restrict__ farr = s ? a.fb : a.fa;

    __shared__ __align__(16) float Xs[128 * 37];
    __shared__ float vsh[2][36];
    __shared__ float ash[2][36];
    __shared__ float csh[2];

    const int tid = threadIdx.x;
    if (tid < 72) {
        int p = tid / 36, k = tid % 36;
        vsh[p][k] = g_v[jb0 + p][k];
        ash[p][k] = (k < EMB) ? a.att[ja0 + p][k] : 0.0f;
    }
    if (tid < 2) csh[tid] = g_c[jb0 + tid];

    const int base  = blockIdx.x * 128;
    const int nrows = min(128, NNODE - base);
    const int total = nrows * EMB;
    {
        const float* __restrict__ src = farr + base * EMB;
        for (int g = tid; g < total; g += 256)
            Xs[(g / EMB) * 37 + (g % EMB)] = src[g];
    }
    __syncthreads();

    const int row_l = tid >> 1;
    const int half  = tid & 1;
    const bool valid = (row_l < nrows);
    const int rl = valid ? row_l : 0;
    const int row = base + rl;
    const float* xrs = Xs + rl * 37;

    float sbe = 0.0f, sbo = 0.0f;
    if (half == 0) {
        float s0 = 0.0f, s1 = 0.0f;
#pragma unroll 7
        for (int k = 0; k < EMB; k++) {
            float xv = xrs[k];
            s0 = fmaf(xv, ash[0][k], s0);
            s1 = fmaf(xv, ash[1][k], s1);
        }
        if (valid) {
            g_sa[ja0][row]     = s0;
            g_sa[ja0 + 1][row] = s1;
        }
    } else {
        sbe = csh[0];
        sbo = csh[1];
#pragma unroll 7
        for (int k = 0; k < EMB; k++) {
            float xv = xrs[k];
            sbe = fmaf(xv, vsh[0][k], sbe);
            sbo = fmaf(xv, vsh[1][k], sbo);
        }
    }

    if (valid) {
        uint* r = reinterpret_cast<uint*>(&g_f16[s][row * NBH]) + 10 * half;
#pragma unroll
        for (int i = 0; i < 10; i++) {
            int i0 = 20 * half + 2 * i;
            float f0, f1;
            f0 = (i0 < EMB) ? xrs[i0] : ((i0 == 35) ? sbe : ((i0 == 36) ? sbo : 0.0f));
            int i1 = i0 + 1;
            f1 = (i1 < EMB) ? xrs[i1] : ((i1 == 35) ? sbe : ((i1 == 36) ? sbo : 0.0f));
            r[i] = h2u(f0, f1);
        }
    }
}

// =====================================================================
// Kernel 2: aggregation over RAW fp16 features (R16 structure);
// output now fp16 rows in g_mh (40 halves; uints 0..17 written, pads 0).
// =====================================================================
__global__ __launch_bounds__(256) void agg_kernel(AArgs args) {
    const int jid = blockIdx.y;
    const __half* __restrict__ nbh16 = g_f16[(jid < 2) ? 1 : 0];
    const ull* __restrict__ nb = reinterpret_cast<const ull*>(nbh16);
    const float* __restrict__ sav = g_sa[jid];
    const int*   __restrict__ dst = args.dst[jid];
    uint* __restrict__ mh = reinterpret_cast<uint*>(g_mh[jid]);
    const int parity = jid & 1;

    __shared__ float sw[8][36];
    __shared__ int   soff[8][36];

    const int wid  = threadIdx.x >> 5;
    const int lane = threadIdx.x & 31;
    const int node = blockIdx.x * 8 + wid;
    if (node >= NNODE) return;

    const int d = dst[node * DEG + lane];
    float sb = __half2float(nbh16[d * NBH + 35 + parity]);
    float x = sav[node] + sb;
    float e = (x > 0.0f) ? x : 0.1f * expm1f(x);   // elu(alpha=0.1)
    float w = expf(e);

    float wsum = w;
#pragma unroll
    for (int o = 16; o; o >>= 1) wsum += __shfl_xor_sync(0xffffffffu, wsum, o);

    sw[wid][lane]   = w;
    soff[wid][lane] = d * 10;
    if (lane == 0) { sw[wid][32] = 0.0f; soff[wid][32] = 0; }
    __syncwarp();

    const int sub   = (lane < 27) ? (lane / 9) : 2;
    const int piece = (lane < 27) ? (lane % 9) : (lane - 27);

    float a0 = 0.0f, a1 = 0.0f, a2 = 0.0f, a3 = 0.0f;
#pragma unroll
    for (int it = 0; it < 11; it++) {
        int j = it * 3 + sub;
        float wj = sw[wid][j];
        ull v = nb[soff[wid][j] + piece];
        uint lo, hi;
        asm("mov.b64 {%0, %1}, %2;" : "=r"(lo), "=r"(hi) : "l"(v));
        float2 f0 = __half22float2(*reinterpret_cast<__half2*>(&lo));
        float2 f1 = __half22float2(*reinterpret_cast<__half2*>(&hi));
        a0 = fmaf(wj, f0.x, a0);
        a1 = fmaf(wj, f0.y, a1);
        a2 = fmaf(wj, f1.x, a2);
        a3 = fmaf(wj, f1.y, a3);
    }

    {
        float t, u;
        t = __shfl_down_sync(0xffffffffu, a0, 9);
        u = __shfl_down_sync(0xffffffffu, a0, 18);
        a0 += t + u;
        t = __shfl_down_sync(0xffffffffu, a1, 9);
        u = __shfl_down_sync(0xffffffffu, a1, 18);
        a1 += t + u;
        t = __shfl_down_sync(0xffffffffu, a2, 9);
        u = __shfl_down_sync(0xffffffffu, a2, 18);
        a2 += t + u;
        t = __shfl_down_sync(0xffffffffu, a3, 9);
        u = __shfl_down_sync(0xffffffffu, a3, 18);
        a3 += t + u;
    }

    if (lane < 9) {
        float inv = 1.0f / wsum;
        uint2 o;
        o.x = h2u(a0 * inv, a1 * inv);
        o.y = h2u(a2 * inv, a3 * inv);
        *reinterpret_cast<uint2*>(mh + node * 20 + 2 * lane) = o;
    }
}

// =====================================================================
// Kernel 3: tensor-core update, copy-only staging.
// Block = 128 nodes, 8 warps; warp owns 16 M-rows and stages them itself
// (27 coalesced LDG.64 + 28 STS.64 per row, zero converts, zero branches).
// X row = 112 halves (28 ull): feat[0,36) | m0[36,72) | m1[72,108) | pad.
// GEMM1 7 ks, PReLU->H in-place (row-local), GEMM2 5 ks. One block barrier.
// =====================================================================
__global__ __launch_bounds__(256) void update_kernel(
    const float* __restrict__ alpha_p,
    const float* __restrict__ b2,
    float* __restrict__ out)
{
    const int side = blockIdx.y;

    __shared__ __align__(16) __half Xh[128 * 112];  // 28672B; reused as H
    __shared__ __align__(16) __half W1T[80 * 112];  // 17920B
    __shared__ __align__(16) __half W2T[40 * 80];   // 6400B

    const int tid = threadIdx.x;

    // ---- stage weights (ull copies, block-cooperative) ----
    {
        const ull* s1 = reinterpret_cast<const ull*>(g_W1fT[side]);
        ull* d1 = reinterpret_cast<ull*>(W1T);
        for (int i = tid; i < 80 * 112 / 4; i += 256) d1[i] = s1[i];
        const ull* s2 = reinterpret_cast<const ull*>(g_W2T);
        ull* d2 = reinterpret_cast<ull*>(W2T);
        for (int i = tid; i < 40 * 80 / 4; i += 256) d2[i] = s2[i];
    }

    const int base = blockIdx.x * 128;
    const int wid  = tid >> 5;
    const int lane = tid & 31;
    const int m0r  = wid * 16;

    // ---- stage own 16 X rows: pure ull copies ----
    {
        ull* Xull = reinterpret_cast<ull*>(Xh);
        const __half* fb0 = g_f16[side];
        const __half* mb0 = g_mh[2 * side];
        const __half* mb1 = g_mh[2 * side + 1];
#pragma unroll
        for (int r = 0; r < 16; r++) {
            int row = m0r + r;
            int n = base + row;
            ull v = 0ull;
            if (lane < 27 && n < NNODE) {
                if (lane < 9)
                    v = reinterpret_cast<const ull*>(fb0 + (size_t)n * NBH)[lane];
                else if (lane < 18)
                    v = reinterpret_cast<const ull*>(mb0 + (size_t)n * 40)[lane - 9];
                else
                    v = reinterpret_cast<const ull*>(mb1 + (size_t)n * 40)[lane - 18];
            }
            if (lane < 28) Xull[row * 28 + lane] = v;
        }
    }
    __syncthreads();   // weights + all X visible

    const int rg = lane >> 2;     // 0..7
    const int cg = lane & 3;      // 0..3
    const float alpha = __ldg(alpha_p);

    const uint* Xu  = reinterpret_cast<const uint*>(Xh);
    const uint* W1u = reinterpret_cast<const uint*>(W1T);
    const uint* W2u = reinterpret_cast<const uint*>(W2T);

    // ---- GEMM1: C1[10 n-tiles][4], init with fused bias ----
    float c1[10][4];
#pragma unroll
    for (int j = 0; j < 10; j++) {
        int col = 8 * j + 2 * cg;
        float b0v = __ldg(&g_b1f[side][col]);
        float b1v = __ldg(&g_b1f[side][col + 1]);
        c1[j][0] = b0v; c1[j][1] = b1v; c1[j][2] = b0v; c1[j][3] = b1v;
    }

#pragma unroll
    for (int ks = 0; ks < 7; ks++) {
        int ab = (m0r + rg) * 56 + 8 * ks + cg;
        uint a0 = Xu[ab];
        uint a1 = Xu[ab + 8 * 56];
        uint a2 = Xu[ab + 4];
        uint a3 = Xu[ab + 8 * 56 + 4];
#pragma unroll
        for (int j = 0; j < 10; j++) {
            int bb = (8 * j + rg) * 56 + 8 * ks + cg;
            uint b0 = W1u[bb];
            uint b1 = W1u[bb + 4];
            MMA16816(c1[j], a0, a1, a2, a3, b0, b1);
        }
    }
    __syncwarp();   // own-row X reads done; rows become H

    // ---- PReLU, store H fp16 in-place (row-local, stride 56 uints) ----
    uint* Hu = reinterpret_cast<uint*>(Xh);
#pragma unroll
    for (int j = 0; j < 10; j++) {
        float h00 = c1[j][0], h01 = c1[j][1], h10 = c1[j][2], h11 = c1[j][3];
        h00 = (h00 > 0.0f) ? h00 : alpha * h00;
        h01 = (h01 > 0.0f) ? h01 : alpha * h01;
        h10 = (h10 > 0.0f) ? h10 : alpha * h10;
        h11 = (h11 > 0.0f) ? h11 : alpha * h11;
        Hu[(m0r + rg) * 56 + 4 * j + cg]     = h2u(h00, h01);
        Hu[(m0r + rg + 8) * 56 + 4 * j + cg] = h2u(h10, h11);
    }
    __syncwarp();

    // ---- GEMM2: C2[5][4], init with b2 ----
    float c2[5][4];
#pragma unroll
    for (int j = 0; j < 5; j++) {
        int col = 8 * j + 2 * cg;
        float b0v = (col < EMB)     ? __ldg(&b2[col])     : 0.0f;
        float b1v = (col + 1 < EMB) ? __ldg(&b2[col + 1]) : 0.0f;
        c2[j][0] = b0v; c2[j][1] = b1v; c2[j][2] = b0v; c2[j][3] = b1v;
    }

#pragma unroll
    for (int ks = 0; ks < 5; ks++) {
        int ab = (m0r + rg) * 56 + 8 * ks + cg;
        uint a0 = Hu[ab];
        uint a1 = Hu[ab + 8 * 56];
        uint a2 = Hu[ab + 4];
        uint a3 = Hu[ab + 8 * 56 + 4];
#pragma unroll
        for (int j = 0; j < 5; j++) {
            int bb = (8 * j + rg) * 40 + 8 * ks + cg;
            uint b0 = W2u[bb];
            uint b1 = W2u[bb + 4];
            MMA16816(c2[j], a0, a1, a2, a3, b0, b1);
        }
    }

    // ---- fragment stores to out ----
#pragma unroll
    for (int p = 0; p < 2; p++) {
        int row = m0r + rg + 8 * p;
        int n = base + row;
        if (n < NNODE) {
            float* orow = out + (size_t)(side * NNODE + n) * EMB;
#pragma unroll
            for (int j = 0; j < 5; j++) {
                int col = 8 * j + 2 * cg;
                if (col < EMB)     orow[col]     = c2[j][2 * p];
                if (col + 1 < EMB) orow[col + 1] = c2[j][2 * p + 1];
            }
        }
    }
}

// =====================================================================
// launch
// =====================================================================
extern "C" void kernel_launch(void* const* d_in, const int* in_sizes, int n_in,
                              void* d_out, int out_size) {
    const float* fa = (const float*)d_in[0];
    const float* fb = (const float*)d_in[1];

    FArgs f;
    for (int j = 0; j < 4; j++) {
        f.W[j]   = (const float*)d_in[6 + 3 * j];
        f.b[j]   = (const float*)d_in[7 + 3 * j];
        f.att[j] = (const float*)d_in[8 + 3 * j];
    }
    f.W1 = (const float*)d_in[18];
    f.b1 = (const float*)d_in[19];
    f.W2 = (const float*)d_in[21];

    CArgs c;
    c.fa = fa;
    c.fb = fb;
    for (int j = 0; j < 4; j++) c.att[j] = f.att[j];

    AArgs a;
    a.dst[0] = (const int*)d_in[2];
    a.dst[1] = (const int*)d_in[3];
    a.dst[2] = (const int*)d_in[4];
    a.dst[3] = (const int*)d_in[5];

    const float* al = (const float*)d_in[20];
    const float* b2 = (const float*)d_in[22];
    float* out = (float*)d_out;

    fuse_kernel<<<2, 256>>>(f);

    dim3 cg((NNODE + 127) / 128, 2);
    cast_kernel<<<cg, 256>>>(c);

    dim3 ag((NNODE + 7) / 8, 4);
    agg_kernel<<<ag, 256>>>(a);

    dim3 ug((NNODE + 127) / 128, 2);
    update_kernel<<<ug, 256>>>(al, b2, out);
}